// round 15
// baseline (speedup 1.0000x reference)
#include <cuda_runtime.h>
#include <cstdint>

#define B 8
#define L 512
#define HID 768
#define NH 12
#define D 64
#define TH 32
#define TE 64
#define TT 96
#define BH (B*NH)
#define ROWS (B*L)

typedef unsigned long long ull;

__device__ __forceinline__ float f2tf32f(float x) {
    uint32_t u; asm("cvt.rna.tf32.f32 %0, %1;" : "=r"(u) : "f"(x));
    return __uint_as_float(u);
}
__device__ __forceinline__ uint32_t smem_u32(const void* p) {
    uint32_t a; asm("{ .reg .u64 t; cvta.to.shared.u64 t, %1; cvt.u32.u64 %0, t; }" : "=r"(a) : "l"(p)); return a;
}
__device__ __forceinline__ void cpasync16(uint32_t saddr, const void* gaddr) {
    asm volatile("cp.async.cg.shared.global [%0], [%1], 16;" :: "r"(saddr), "l"(gaddr));
}
__device__ __forceinline__ void redadd(float* p, float v) {
    asm volatile("red.global.add.f32 [%0], %1;" :: "l"(p), "f"(v) : "memory");
}
__device__ __forceinline__ void mma_tf32(float* d, const uint32_t* a, const uint32_t* b) {
    asm volatile(
        "mma.sync.aligned.m16n8k8.row.col.f32.tf32.tf32.f32 "
        "{%0,%1,%2,%3}, {%4,%5,%6,%7}, {%8,%9}, {%0,%1,%2,%3};"
        : "+f"(d[0]), "+f"(d[1]), "+f"(d[2]), "+f"(d[3])
        : "r"(a[0]), "r"(a[1]), "r"(a[2]), "r"(a[3]), "r"(b[0]), "r"(b[1]));
}

// ---------------- scratch ----------------
__device__ float g_Q[BH*L*D];
__device__ float g_K[BH*L*D];
__device__ float g_V[BH*L*D];
__device__ float g_P[BH*L*TT];
__device__ float g_AO[ROWS*HID];
__device__ float g_WT[4*HID*HID];
__device__ float g_X32[ROWS*HID];
__device__ float g_binsG[BH*(L/32)*32*TT];   // per-block gmem bins (REDG target)

// ---------------- rounding kernel ----------------
__global__ __launch_bounds__(256) void round_kernel(
    const float* __restrict__ src, float* __restrict__ dst)
{
    int i = blockIdx.x * 256 + threadIdx.x;
    float4 v = ((const float4*)src)[i];
    v.x = f2tf32f(v.x); v.y = f2tf32f(v.y); v.z = f2tf32f(v.z); v.w = f2tf32f(v.w);
    ((float4*)dst)[i] = v;
}

// ---------------- fused W transposes (+tf32 round) ----------------
__global__ __launch_bounds__(256) void transpose4_kernel(
    const float* __restrict__ W0, const float* __restrict__ W1,
    const float* __restrict__ W2, const float* __restrict__ W3,
    float* __restrict__ Wdst)
{
    __shared__ float t[32][33];
    const float* Wsrc = (blockIdx.z == 0) ? W0 : (blockIdx.z == 1) ? W1
                       : (blockIdx.z == 2) ? W2 : W3;
    float* Wout = Wdst + (size_t)blockIdx.z * HID * HID;
    int x  = blockIdx.x * 32 + threadIdx.x;
    int y0 = blockIdx.y * 32 + threadIdx.y;
#pragma unroll
    for (int dy = 0; dy < 32; dy += 8)
        t[threadIdx.y + dy][threadIdx.x] = f2tf32f(Wsrc[(size_t)(y0 + dy) * HID + x]);
    __syncthreads();
    int xo  = blockIdx.y * 32 + threadIdx.x;
    int yo0 = blockIdx.x * 32 + threadIdx.y;
#pragma unroll
    for (int dy = 0; dy < 32; dy += 8)
        Wout[(size_t)(yo0 + dy) * HID + xo] = t[threadIdx.x][threadIdx.y + dy];
}

// ---------------- tf32 mma GEMM, cp.async 2-stage, fused over W -----------
#define KC 32
#define KCP 36
#define NCHUNK (HID/KC)
#define SSZ (128*KCP)

__global__ __launch_bounds__(256, 2) void gemm_mma_kernel(
    const float* __restrict__ A, const float* __restrict__ WTbase,
    const float* __restrict__ b0, const float* __restrict__ b1, const float* __restrict__ b2,
    float* __restrict__ o0, float* __restrict__ o1, float* __restrict__ o2,
    int nbW, int headLayout)
{
    extern __shared__ float smem[];
    const uint32_t sbase = smem_u32(smem);

    const int tid = threadIdx.x;
    const int wid = tid >> 5, lane = tid & 31;
    const int g = lane >> 2, t = lane & 3;
    const int warp_m = wid & 3;
    const int warp_n = wid >> 2;
    const int row0 = blockIdx.x * 128;
    const int by = blockIdx.y;
    const int wsel = by / nbW;
    const int col0 = (by % nbW) * 128;

    const float* WT = WTbase + (size_t)wsel * HID * HID;
    const float* bias = (wsel == 0) ? b0 : (wsel == 1 ? b1 : b2);
    float* Cout = (wsel == 0) ? o0 : (wsel == 1 ? o1 : o2);

    const int sr = tid >> 3;
    const int sv = (tid & 7) << 2;

    float acc[2][8][4];
#pragma unroll
    for (int mf = 0; mf < 2; ++mf)
#pragma unroll
        for (int nf = 0; nf < 8; ++nf)
#pragma unroll
            for (int c = 0; c < 4; ++c) acc[mf][nf][c] = 0.f;

    const int mbase = warp_m * 32;
    const int nbase = warp_n * 64;

    auto issue = [&](int c, int s) {
        uint32_t as = sbase + (uint32_t)(s * 2 * SSZ) * 4u;
        uint32_t bs = as + (uint32_t)SSZ * 4u;
        int k0 = c * KC;
#pragma unroll
        for (int it = 0; it < 4; ++it) {
            int r = sr + it * 32;
            uint32_t so = (uint32_t)(r * KCP + sv) * 4u;
            cpasync16(as + so, &A [(size_t)(row0 + r) * HID + k0 + sv]);
            cpasync16(bs + so, &WT[(size_t)(col0 + r) * HID + k0 + sv]);
        }
        asm volatile("cp.async.commit_group;" ::: "memory");
    };

    issue(0, 0);
    issue(1, 1);

    for (int c = 0; c < NCHUNK; ++c) {
        int s = c & 1;
        if (c < NCHUNK - 2) asm volatile("cp.async.wait_group 1;" ::: "memory");
        else                asm volatile("cp.async.wait_group 0;" ::: "memory");
        __syncthreads();

        const float* As = smem + s * 2 * SSZ;
        const float* Bs = As + SSZ;

#pragma unroll
        for (int kk = 0; kk < KC; kk += 8) {
            uint32_t bfr[8][2];
#pragma unroll
            for (int nf = 0; nf < 8; ++nf) {
                const float* bp = &Bs[(nbase + nf * 8 + g) * KCP + kk + t];
                bfr[nf][0] = __float_as_uint(bp[0]);
                bfr[nf][1] = __float_as_uint(bp[4]);
            }
            uint32_t afr[2][4];
#pragma unroll
            for (int mf = 0; mf < 2; ++mf) {
                const float* ap = &As[(mbase + mf * 16 + g) * KCP + kk + t];
                afr[mf][0] = __float_as_uint(ap[0]);
                afr[mf][1] = __float_as_uint(ap[8 * KCP]);
                afr[mf][2] = __float_as_uint(ap[4]);
                afr[mf][3] = __float_as_uint(ap[8 * KCP + 4]);
            }
#pragma unroll
            for (int mf = 0; mf < 2; ++mf)
#pragma unroll
                for (int nf = 0; nf < 8; ++nf)
                    mma_tf32(acc[mf][nf], afr[mf], bfr[nf]);
        }
        __syncthreads();
        if (c + 2 < NCHUNK) issue(c + 2, s);
    }

#pragma unroll
    for (int mf = 0; mf < 2; ++mf) {
#pragma unroll
        for (int nf = 0; nf < 8; ++nf) {
            int row_a = row0 + mbase + mf * 16 + g;
            int col_a = col0 + nbase + nf * 8 + 2 * t;
#pragma unroll
            for (int half = 0; half < 2; ++half) {
                int row = row_a + half * 8;
                float2 v;
                v.x = acc[mf][nf][2 * half]     + bias[col_a];
                v.y = acc[mf][nf][2 * half + 1] + bias[col_a + 1];
                if (headLayout) {
                    int bb2 = row >> 9, ll = row & 511, hh = col_a >> 6, dd = col_a & 63;
                    *(float2*)&Cout[(((size_t)bb2 * NH + hh) * L + ll) * D + dd] = v;
                } else {
                    *(float2*)&Cout[(size_t)row * HID + col_a] = v;
                }
            }
        }
    }
}

// ---------------- proj via mma (unchanged) ----------------
__global__ __launch_bounds__(256) void proj_mma_kernel(
    const float* __restrict__ qh, const float* __restrict__ qe,
    const float* __restrict__ kh, const float* __restrict__ ke)
{
    __shared__ float As[128 * KCP];
    __shared__ float Bs[TT * KCP];

    const int tid = threadIdx.x;
    const int wid = tid >> 5, lane = tid & 31;
    const int g = lane >> 2, t = lane & 3;
    const int warp_m = wid & 3;
    const int warp_n = wid >> 2;
    const int l0 = blockIdx.x * 128;
    const int bh = blockIdx.y;
    const int h  = bh % NH;

    float acc[2][6][4];
#pragma unroll
    for (int mf = 0; mf < 2; ++mf)
#pragma unroll
        for (int nf = 0; nf < 6; ++nf)
#pragma unroll
            for (int c = 0; c < 4; ++c) acc[mf][nf][c] = 0.f;

    const int mbase = warp_m * 32;
    const int nbase = warp_n * 48;

    for (int c = 0; c < 4; ++c) {
        const float* Asrc = (c < 2 ? g_Q : g_K) + ((size_t)bh * L + l0) * D + (c & 1) * 32;
        const float* E1 = (c < 2) ? qh : kh;
        const float* E2 = (c < 2) ? qe : ke;
        const int koff = h * D + (c & 1) * 32;

#pragma unroll
        for (int it = 0; it < 4; ++it) {
            int idx = tid + it * 256;
            int r = idx >> 3, v = (idx & 7) << 2;
            float4 a = *(const float4*)&Asrc[(size_t)r * D + v];
            float* da = &As[r * KCP + v];
            da[0] = f2tf32f(a.x); da[1] = f2tf32f(a.y);
            da[2] = f2tf32f(a.z); da[3] = f2tf32f(a.w);
        }
#pragma unroll
        for (int it = 0; it < 3; ++it) {
            int idx = tid + it * 256;
            int r = idx >> 3, v = (idx & 7) << 2;
            const float* src = (r < TH) ? &E1[(size_t)r * HID + koff + v]
                                        : &E2[(size_t)(r - TH) * HID + koff + v];
            float4 b = *(const float4*)src;
            float* db = &Bs[r * KCP + v];
            db[0] = f2tf32f(b.x); db[1] = f2tf32f(b.y);
            db[2] = f2tf32f(b.z); db[3] = f2tf32f(b.w);
        }
        __syncthreads();

#pragma unroll
        for (int kk = 0; kk < KC; kk += 8) {
            uint32_t bfr[6][2];
#pragma unroll
            for (int nf = 0; nf < 6; ++nf) {
                const float* bp = &Bs[(nbase + nf * 8 + g) * KCP + kk + t];
                bfr[nf][0] = __float_as_uint(bp[0]);
                bfr[nf][1] = __float_as_uint(bp[4]);
            }
            uint32_t afr[2][4];
#pragma unroll
            for (int mf = 0; mf < 2; ++mf) {
                const float* ap = &As[(mbase + mf * 16 + g) * KCP + kk + t];
                afr[mf][0] = __float_as_uint(ap[0]);
                afr[mf][1] = __float_as_uint(ap[8 * KCP]);
                afr[mf][2] = __float_as_uint(ap[4]);
                afr[mf][3] = __float_as_uint(ap[8 * KCP + 4]);
            }
#pragma unroll
            for (int mf = 0; mf < 2; ++mf)
#pragma unroll
                for (int nf = 0; nf < 6; ++nf)
                    mma_tf32(acc[mf][nf], afr[mf], bfr[nf]);
        }
        __syncthreads();
    }

    float* Pout = g_P + ((size_t)bh * L + l0) * TT;
#pragma unroll
    for (int mf = 0; mf < 2; ++mf) {
#pragma unroll
        for (int nf = 0; nf < 6; ++nf) {
            int row_a = mbase + mf * 16 + g;
            int col_a = nbase + nf * 8 + 2 * t;
#pragma unroll
            for (int half = 0; half < 2; ++half) {
                int row = row_a + half * 8;
                float2 v;
                v.x = acc[mf][nf][2 * half];
                v.y = acc[mf][nf][2 * half + 1];
                *(float2*)&Pout[(size_t)row * TT + col_a] = v;
            }
        }
    }
}

// ---------------- attention: mma phases + REDG gmem bin scatter ------------
#define AT_ROWS 32
#define QS_STR 68
#define KB_STR 68
#define VT_STR 132
#define ES_STR 132
#define BIN_STR 100
#define ATT_SMEM_FLOATS (AT_ROWS*QS_STR + AT_ROWS*TT + AT_ROWS*ES_STR + 128*KB_STR + 32)

__global__ __launch_bounds__(512) void attn_kernel(
    const int* __restrict__ hop, const int* __restrict__ edge,
    const float* __restrict__ vh, const float* __restrict__ ve)
{
    extern __shared__ float sm[];
    float* qs   = sm;                            // [32][68] tf32 Q
    float* Ps   = qs + AT_ROWS * QS_STR;         // [32][96]
    float* es   = Ps + AT_ROWS * TT;             // [32][132] tf32 e
    float* buf  = es + AT_ROWS * ES_STR;         // K rows / V^T / VE / reduce
    float* rs   = buf + 128 * KB_STR;            // [32]
    float* binsC = es;                           // overlay after main loop: [32][100]

    const int bh = blockIdx.y;
    const int bb = bh / NH, h = bh % NH;
    const int i0 = blockIdx.x * AT_ROWS;
    const int tid = threadIdx.x;
    const int wid = tid >> 5, lane = tid & 31;
    const int g = lane >> 2, t = lane & 3;
    const float scale = 0.125f;

    // per-block private gmem bins
    float* gb = g_binsG + ((size_t)(bh * (L / AT_ROWS) + blockIdx.x)) * AT_ROWS * TT;

    {
        const float* Qp = g_Q + ((size_t)bh * L + i0) * D;
        for (int idx = tid; idx < AT_ROWS * D; idx += 512) {
            int row = idx >> 6, dd = idx & 63;
            qs[row * QS_STR + dd] = f2tf32f(Qp[idx]);
        }
        const float* Pp = g_P + ((size_t)bh * L + i0) * TT;
        for (int idx = tid; idx < AT_ROWS * TT; idx += 512) Ps[idx] = Pp[idx];
        for (int idx = tid; idx < AT_ROWS * TT; idx += 512) gb[idx] = 0.f;
        if (tid < 32) rs[tid] = 0.f;
    }
    __threadfence();
    __syncthreads();

    const size_t hopBase = ((size_t)bb * L + i0) * L;
    const int nsc = wid * 8;          // scores: 8 cols per warp
    const int nav = (wid & 7) * 8;    // AV/VE: 8 d-cols, k split by jh
    const int jh  = wid >> 3;

    float oacc[2][4];
#pragma unroll
    for (int mf = 0; mf < 2; ++mf)
#pragma unroll
        for (int c = 0; c < 4; ++c) oacc[mf][c] = 0.f;
    float lsum[4] = {0.f, 0.f, 0.f, 0.f};

    for (int jc = 0; jc < L; jc += 128) {
        // ---- stage K chunk rows (tf32): buf[j][d], stride 68 ----
        {
            const float* Kp = g_K + ((size_t)bh * L + jc) * D;
            for (int idx4 = tid; idx4 < 2048; idx4 += 512) {
                int jj = idx4 >> 4, dd4 = (idx4 & 15) << 2;
                float4 kv = *(const float4*)&Kp[(size_t)jj * D + dd4];
                kv.x = f2tf32f(kv.x); kv.y = f2tf32f(kv.y);
                kv.z = f2tf32f(kv.z); kv.w = f2tf32f(kv.w);
                *(float4*)&buf[jj * KB_STR + dd4] = kv;
            }
        }
        __syncthreads();

        // ---- prefetch hop/edge gathers ----
        int2 hpre[2][2], epre[2][2];
        {
            int jl = nsc + 2 * t;
#pragma unroll
            for (int mf = 0; mf < 2; ++mf)
#pragma unroll
                for (int half = 0; half < 2; ++half) {
                    int i = mf * 16 + half * 8 + g;
                    size_t a = hopBase + (size_t)i * L + jc + jl;
                    hpre[mf][half] = *(const int2*)&hop [a];
                    epre[mf][half] = *(const int2*)&edge[a];
                }
        }

        // ---- scores mma ----
        float sacc[2][4];
#pragma unroll
        for (int mf = 0; mf < 2; ++mf)
#pragma unroll
            for (int c = 0; c < 4; ++c) sacc[mf][c] = 0.f;

#pragma unroll
        for (int ks = 0; ks < 8; ++ks) {
            int kk = ks * 8;
            uint32_t afr[2][4];
#pragma unroll
            for (int mf = 0; mf < 2; ++mf) {
                const float* ap = &qs[(mf * 16 + g) * QS_STR + kk + t];
                afr[mf][0] = __float_as_uint(ap[0]);
                afr[mf][1] = __float_as_uint(ap[8 * QS_STR]);
                afr[mf][2] = __float_as_uint(ap[4]);
                afr[mf][3] = __float_as_uint(ap[8 * QS_STR + 4]);
            }
            uint32_t bfr[2];
            {
                const float* bp = &buf[(nsc + g) * KB_STR + kk + t];
                bfr[0] = __float_as_uint(bp[0]);
                bfr[1] = __float_as_uint(bp[4]);
            }
#pragma unroll
            for (int mf = 0; mf < 2; ++mf)
                mma_tf32(sacc[mf], afr[mf], bfr);
        }

        // ---- bias add + exp + es store + REDG bin scatter ----
        {
            int jl = nsc + 2 * t;
#pragma unroll
            for (int mf = 0; mf < 2; ++mf) {
#pragma unroll
                for (int half = 0; half < 2; ++half) {
                    int i = mf * 16 + half * 8 + g;
                    const int2 hp = hpre[mf][half];
                    const int2 ep = epre[mf][half];
                    const float* prow = Ps + i * TT;
                    float s0 = (sacc[mf][2*half]   + prow[hp.x] + prow[TH + ep.x]) * scale;
                    float s1 = (sacc[mf][2*half+1] + prow[hp.y] + prow[TH + ep.y]) * scale;
                    float e0 = __expf(fminf(fmaxf(s0, -70.f), 70.f));
                    float e1 = __expf(fminf(fmaxf(s1, -70.f), 70.f));
                    float2 ev = make_float2(f2tf32f(e0), f2tf32f(e1));
                    *(float2*)&es[i * ES_STR + jl] = ev;
                    lsum[mf * 2 + half] += e0 + e1;
                    float* brow = gb + i * TT;
                    redadd(&brow[hp.x], e0);  redadd(&brow[TH + ep.x], e0);
                    redadd(&brow[hp.y], e1);  redadd(&brow[TH + ep.y], e1);
                }
            }
        }
        __syncthreads();   // es complete; buf free

        // ---- stage V^T (tf32): buf[d][j], stride 132 ----
        {
            const float* Vp = g_V + ((size_t)bh * L + jc) * D;
            for (int idx4 = tid; idx4 < 2048; idx4 += 512) {
                int jj = idx4 >> 4, dd4 = (idx4 & 15) << 2;
                float4 vv = *(const float4*)&Vp[(size_t)jj * D + dd4];
                buf[(dd4 + 0) * VT_STR + jj] = f2tf32f(vv.x);
                buf[(dd4 + 1) * VT_STR + jj] = f2tf32f(vv.y);
                buf[(dd4 + 2) * VT_STR + jj] = f2tf32f(vv.z);
                buf[(dd4 + 3) * VT_STR + jj] = f2tf32f(vv.w);
            }
        }
        __syncthreads();

        // ---- AV mma: k-half jh covers j = jh*64..+64 ----
#pragma unroll
        for (int ks = 0; ks < 8; ++ks) {
            int kk = jh * 64 + ks * 8;
            uint32_t bfr[2];
            {
                const float* bp = &buf[(nav + g) * VT_STR + kk + t];
                bfr[0] = __float_as_uint(bp[0]);
                bfr[1] = __float_as_uint(bp[4]);
            }
#pragma unroll
            for (int mf = 0; mf < 2; ++mf) {
                uint32_t afr[4];
                const float* ap = &es[(mf * 16 + g) * ES_STR + kk + t];
                afr[0] = __float_as_uint(ap[0]);
                afr[1] = __float_as_uint(ap[8 * ES_STR]);
                afr[2] = __float_as_uint(ap[4]);
                afr[3] = __float_as_uint(ap[8 * ES_STR + 4]);
                mma_tf32(oacc[mf], afr, bfr);
            }
        }
        __syncthreads();   // es + buf free for next chunk
    }

    // ---- make all REDGs from this block visible, then row sums ----
    __threadfence();
    atomicAdd(&rs[g],      lsum[0]);
    atomicAdd(&rs[g + 8],  lsum[1]);
    atomicAdd(&rs[16 + g], lsum[2]);
    atomicAdd(&rs[24 + g], lsum[3]);
    __syncthreads();

    // ---- load bins from gmem (round) -> binsC; stage VE ----
    for (int idx = tid; idx < AT_ROWS * TT; idx += 512) {
        int row = idx / TT, tt = idx % TT;
        binsC[row * BIN_STR + tt] = f2tf32f(gb[idx]);
    }
    for (int idx = tid; idx < TT * D; idx += 512) {
        int tt = idx >> 6, d2 = idx & 63;
        float v = (tt < TH) ? vh[(size_t)tt * HID + h * D + d2]
                            : ve[(size_t)(tt - TH) * HID + h * D + d2];
        buf[d2 * BIN_STR + tt] = f2tf32f(v);
    }
    __syncthreads();

    // ---- bins x VE mma: k-half jh covers t = jh*48..+48 ----
#pragma unroll
    for (int ks = 0; ks < 6; ++ks) {
        int kk = jh * 48 + ks * 8;
        uint32_t bfr[2];
        {
            const float* bp = &buf[(nav + g) * BIN_STR + kk + t];
            bfr[0] = __float_as_uint(bp[0]);
            bfr[1] = __float_as_uint(bp[4]);
        }
#pragma unroll
        for (int mf = 0; mf < 2; ++mf) {
            uint32_t afr[4];
            const float* ap = &binsC[(mf * 16 + g) * BIN_STR + kk + t];
            afr[0] = __float_as_uint(ap[0]);
            afr[1] = __float_as_uint(ap[8 * BIN_STR]);
            afr[2] = __float_as_uint(ap[4]);
            afr[3] = __float_as_uint(ap[8 * BIN_STR + 4]);
            mma_tf32(oacc[mf], afr, bfr);
        }
    }
    __syncthreads();

    // ---- reduce the two k-half partials via smem (buf reused) ----
    if (jh == 1) {
#pragma unroll
        for (int mf = 0; mf < 2; ++mf)
#pragma unroll
            for (int half = 0; half < 2; ++half) {
                int i = mf * 16 + half * 8 + g;
                *(float2*)&buf[i * KB_STR + nav + 2 * t] =
                    make_float2(oacc[mf][2 * half], oacc[mf][2 * half + 1]);
            }
    }
    __syncthreads();
    if (jh == 0) {
#pragma unroll
        for (int mf = 0; mf < 2; ++mf)
#pragma unroll
            for (int half = 0; half < 2; ++half) {
                int i = mf * 16 + half * 8 + g;
                float rinv = 1.f / rs[i];
                float2 p = *(const float2*)&buf[i * KB_STR + nav + 2 * t];
                float2 v;
                v.x = f2tf32f((oacc[mf][2 * half]     + p.x) * rinv);
                v.y = f2tf32f((oacc[mf][2 * half + 1] + p.y) * rinv);
                *(float2*)&g_AO[((size_t)bb * L + i0 + i) * HID + h * D + nav + 2 * t] = v;
            }
    }
}

// --------------------------------------------------------------------------
extern "C" void kernel_launch(void* const* d_in, const int* in_sizes, int n_in,
                              void* d_out, int out_size)
{
    const float* x   = (const float*)d_in[0];
    const float* qh  = (const float*)d_in[1];
    const float* qe  = (const float*)d_in[2];
    const float* kh  = (const float*)d_in[3];
    const float* ke  = (const float*)d_in[4];
    const float* vh  = (const float*)d_in[5];
    const float* ve  = (const float*)d_in[6];
    const int*   hop = (const int*)d_in[7];
    const int*   edg = (const int*)d_in[8];
    const float* Wq = (const float*)d_in[9];   const float* bq = (const float*)d_in[10];
    const float* Wk = (const float*)d_in[11];  const float* bk = (const float*)d_in[12];
    const float* Wv = (const float*)d_in[13];  const float* bv = (const float*)d_in[14];
    const float* Wo = (const float*)d_in[15];  const float* bo = (const float*)d_in[16];
    float* out = (float*)d_out;

    float *Qp, *Kp, *Vp, *AOp, *WTp, *X32p;
    cudaGetSymbolAddress((void**)&Qp,  g_Q);
    cudaGetSymbolAddress((void**)&Kp,  g_K);
    cudaGetSymbolAddress((void**)&Vp,  g_V);
    cudaGetSymbolAddress((void**)&AOp, g_AO);
    cudaGetSymbolAddress((void**)&WTp, g_WT);
    cudaGetSymbolAddress((void**)&X32p, g_X32);

    const int attSmem  = ATT_SMEM_FLOATS * (int)sizeof(float);
    const int gemmSmem = 4 * SSZ * (int)sizeof(float);
    cudaFuncSetAttribute(attn_kernel, cudaFuncAttributeMaxDynamicSharedMemorySize, attSmem);
    cudaFuncSetAttribute(gemm_mma_kernel, cudaFuncAttributeMaxDynamicSharedMemorySize, gemmSmem);

    round_kernel<<<ROWS * HID / 1024, 256>>>(x, X32p);
    transpose4_kernel<<<dim3(HID / 32, HID / 32, 4), dim3(32, 8)>>>(Wq, Wk, Wv, Wo, WTp);

    gemm_mma_kernel<<<dim3(ROWS / 128, 18), 256, gemmSmem>>>(
        X32p, WTp, bq, bk, bv, Qp, Kp, Vp, 6, 1);

    proj_mma_kernel<<<dim3(L / 128, BH), 256>>>(qh, qe, kh, ke);
    attn_kernel<<<dim3(L / AT_ROWS, BH), 512, attSmem>>>(hop, edg, vh, ve);

    gemm_mma_kernel<<<dim3(ROWS / 128, 6), 256, gemmSmem>>>(
        AOp, WTp + 3 * (size_t)HID * HID, bo, bo, bo, out, out, out, 6, 0);
}